// round 15
// baseline (speedup 1.0000x reference)
#include <cuda_runtime.h>

// SparseMCFModel — math reduction (validated over 13 passing rounds):
//  * decoder softmax has identical logits within each segment
//    => w[e] = 1/out_degree(edge_row[e]) EXACTLY. GAT/GRU/decoder dead code.
//  * recurrence: x_1 = relu(demands);
//      x_{t+1}[n] = dpos[n] + sum_{e: col(e)=n} w[e]*x_t[row(e)]
//      flow[e]    = w[e] * x_10[row(e)]
//
// Structure: PDL-chained 11-node graph, FULL-WAVE grids (1 edge/thread,
// 782 blocks x 256 — best measured config, R12=41.0us).
// Safety (R13 lesson): pdl_trigger strictly AFTER pdl_wait in dependent
// kernels => at most 2 generations overlap. 4-buffer rotation: step t reads
// x[(t-1)%4], writes x[t%4], resets x[(t+1)%4]; concurrent step t-1 touches
// {t-2,t-1,t}%4 — disjoint from the reset => all resets pre-wait, race-free.
// d_w written only by step 1 => pre-wait load from step 3 on (step 2 is a
// specialized kernel that loads w post-wait).

#define NN 20000
#define NE 200000
#define BS 256
#define GE ((NE + BS - 1) / BS)   // 782 blocks (full wave); covers NN too

__device__ float d_dpos[NN];
__device__ float d_x[4][NN];
__device__ int   d_deg[NN];   // zero at replay start (static init / k_final rezero)
__device__ float d_w[NE];     // per-edge weight (written by k_upd_first only)

__device__ __forceinline__ void pdl_trigger() {
    asm volatile("griddepcontrol.launch_dependents;" ::: "memory");
}
__device__ __forceinline__ void pdl_wait() {
    asm volatile("griddepcontrol.wait;" ::: "memory");
}

// node 1: node-init (x[0..2] = dpos, float2) + degree histogram.
// Early trigger OK: dependent's pre-wait reads only pure harness inputs.
__global__ void __launch_bounds__(BS) k_init_deg(const float* __restrict__ demands,
                                                 const int* __restrict__ row) {
    int i = blockIdx.x * BS + threadIdx.x;
    pdl_trigger();
    if (i < NN / 2) {
        float2 d = __ldg((const float2*)demands + i);
        d.x = d.x > 0.0f ? d.x : 0.0f;
        d.y = d.y > 0.0f ? d.y : 0.0f;
        ((float2*)d_dpos)[i] = d;
        ((float2*)d_x[0])[i] = d;     // x_1 (read buffer of step 1)
        ((float2*)d_x[1])[i] = d;     // step 1 write target, pre-reset
        ((float2*)d_x[2])[i] = d;     // step 2 write target, pre-reset
    }
    if (i < NE) atomicAdd(&d_deg[__ldg(&row[i])], 1);
}

// node 2 (step 1): x_1 -> x_2 + weight precompute. Pre-wait: pure inputs only.
__global__ void __launch_bounds__(BS) k_upd_first(const int* __restrict__ row,
                                                  const int* __restrict__ col) {
    int i = blockIdx.x * BS + threadIdx.x;
    int r = 0, c = 0;
    if (i < NE) { r = __ldg(&row[i]); c = __ldg(&col[i]); }
    pdl_wait();                            // init + deg complete + visible
    pdl_trigger();                         // release step 2's pre-wait
    if (i < NE) {
        float w = 1.0f / (float)d_deg[r];
        d_w[i] = w;
        atomicAdd(&d_x[1][c], w * d_x[0][r]);   // fire-and-forget RED
    }
}

// node 3 (step 2): specialized — w loaded POST-wait (writer is predecessor).
// Pre-wait: pure inputs + reset x[3] (untouched by step 1: {0,1}).
__global__ void __launch_bounds__(BS) k_upd2(const int* __restrict__ row,
                                             const int* __restrict__ col) {
    int i = blockIdx.x * BS + threadIdx.x;
    int r = 0, c = 0;
    if (i < NE) { r = __ldg(&row[i]); c = __ldg(&col[i]); }
    if (i < NN / 2) ((float2*)d_x[3])[i] = ((const float2*)d_dpos)[i];
    pdl_wait();                            // step 1 complete + visible
    pdl_trigger();
    if (i < NE) {
        float w  = d_w[i];
        float xv = __ldg(&d_x[1][r]);      // ONE random gather
        atomicAdd(&d_x[2][c], w * xv);     // ONE fire-and-forget RED
    }
}

// nodes 4..10 (steps 3..9): generic, w pre-wait (immutable since step 1).
// Pre-wait overlaps only step t-1 (trigger-after-wait): resets x[(t+1)%4],
// disjoint from t-1's buffer set {t-2,t-1,t}%4.
__global__ void __launch_bounds__(BS) k_update(const int* __restrict__ row,
                                               const int* __restrict__ col,
                                               int cur, int nxt, int rst) {
    int i = blockIdx.x * BS + threadIdx.x;
    int r = 0, c = 0;
    float w = 0.0f;
    if (i < NE) {
        r = __ldg(&row[i]); c = __ldg(&col[i]);
        w = d_w[i];                        // immutable: safe pre-wait
    }
    if (i < NN / 2) ((float2*)d_x[rst])[i] = ((const float2*)d_dpos)[i];
    pdl_wait();                            // step t-1 complete + visible
    pdl_trigger();
    if (i < NE) {
        float xv = __ldg(&d_x[cur][r]);    // ONE random gather (post-wait)
        atomicAdd(&d_x[nxt][c], w * xv);   // ONE fire-and-forget RED
    }
}

// node 11: flow = w * x_10[row]. Pre-wait: inputs, w (immutable), deg rezero.
__global__ void __launch_bounds__(BS) k_final(const int* __restrict__ row,
                                              float* __restrict__ out, int cur) {
    int e = blockIdx.x * BS + threadIdx.x;
    int r = 0; float w = 0.0f;
    if (e < NE) { r = __ldg(&row[e]); w = d_w[e]; }
    if (e < NN) d_deg[e] = 0;              // rezero for next replay
    pdl_wait();
    if (e < NE) out[e] = w * __ldg(&d_x[cur][r]);
}

static inline void launch_pdl(const void* fn, void** args) {
    cudaLaunchConfig_t cfg = {};
    cfg.gridDim  = dim3(GE);
    cfg.blockDim = dim3(BS);
    cfg.dynamicSmemBytes = 0;
    cfg.stream = 0;
    cudaLaunchAttribute at;
    at.id = cudaLaunchAttributeProgrammaticStreamSerialization;
    at.val.programmaticStreamSerializationAllowed = 1;
    cfg.attrs = &at;
    cfg.numAttrs = 1;
    if (cudaLaunchKernelExC(&cfg, fn, args) != cudaSuccess) {
        cudaGetLastError();
        cfg.numAttrs = 0;                  // fallback: serialized launch (wait is benign)
        cudaLaunchKernelExC(&cfg, fn, args);
    }
}

extern "C" void kernel_launch(void* const* d_in, const int* in_sizes, int n_in,
                              void* d_out, int out_size) {
    // Inputs: node_embeddings, demands, edge_row, edge_col, W_gat, a_src,
    //         a_dst, Wx, Wh, b_gru, Wd, bd
    const float* demands = (const float*)d_in[1];
    const int*   erow    = (const int*)d_in[2];
    const int*   ecol    = (const int*)d_in[3];
    float*       out     = (float*)d_out;

    k_init_deg<<<GE, BS>>>(demands, erow);

    {
        void* args[2] = { (void*)&erow, (void*)&ecol };
        launch_pdl((const void*)k_upd_first, args);
    }
    {
        void* args[2] = { (void*)&erow, (void*)&ecol };
        launch_pdl((const void*)k_upd2, args);
    }

    // steps 3..9: read x[(t-1)%4], write x[t%4], reset x[(t+1)%4]
    for (int t = 3; t <= 9; t++) {
        int cur = (t - 1) & 3, nxt = t & 3, rst = (t + 1) & 3;
        void* args[5] = { (void*)&erow, (void*)&ecol, &cur, &nxt, &rst };
        launch_pdl((const void*)k_update, args);
    }

    {
        int cur = 9 & 3;   // x_10 lives in d_x[1]
        void* args[3] = { (void*)&erow, (void*)&out, &cur };
        launch_pdl((const void*)k_final, args);
    }
}